// round 14
// baseline (speedup 1.0000x reference)
#include <cuda_runtime.h>
#include <cuda_fp16.h>
#include <math.h>
#include <stdint.h>

#define L_SEQ 2048
#define B_SZ  16
#define H_DIM 512
#define NS    32
#define BH    (B_SZ*H_DIM)
#define LBH   (L_SEQ*B_SZ*H_DIM)

__device__ float  g_un[LBH];              // LN output, (L,B,H)
__device__ __half g_yh[LBH];              // gelu output, (B,L,H), fp16
__device__ __half g_wh[2*H_DIM*H_DIM];    // W, fp16
__device__ float g_rr[H_DIM*NS], g_ri[H_DIM*NS], g_cr[H_DIM*NS], g_ci[H_DIM*NS];

typedef unsigned long long ull;

__device__ __forceinline__ uint32_t smem_u32(const void* p) {
    uint32_t a;
    asm("{ .reg .u64 t; cvta.to.shared.u64 t, %1; cvt.u32.u64 %0, t; }" : "=r"(a) : "l"(p));
    return a;
}
__device__ __forceinline__ ull pk(float lo, float hi) {
    ull r; asm("mov.b64 %0, {%1, %2};" : "=l"(r) : "f"(lo), "f"(hi)); return r;
}
__device__ __forceinline__ void upk(float& lo, float& hi, ull v) {
    asm("mov.b64 {%0, %1}, %2;" : "=f"(lo), "=f"(hi) : "l"(v));
}
__device__ __forceinline__ ull f2fma(ull a, ull b, ull c) {
    ull r; asm("fma.rn.f32x2 %0, %1, %2, %3;" : "=l"(r) : "l"(a), "l"(b), "l"(c)); return r;
}
__device__ __forceinline__ ull f2mul(ull a, ull b) {
    ull r; asm("mul.rn.f32x2 %0, %1, %2;" : "=l"(r) : "l"(a), "l"(b)); return r;
}
__device__ __forceinline__ ull f2add(ull a, ull b) {
    ull r; asm("add.rn.f32x2 %0, %1, %2;" : "=l"(r) : "l"(a), "l"(b)); return r;
}

// ---------------- K0: SSM constants ----------------
__global__ void const_kernel(const float* __restrict__ log_dt, const float* __restrict__ C,
                             const float* __restrict__ log_A_real, const float* __restrict__ A_imag) {
    int idx = blockIdx.x*blockDim.x + threadIdx.x;
    if (idx >= H_DIM*NS) return;
    int h = idx >> 5;
    float dt  = expf(log_dt[h]);
    float Are = -expf(log_A_real[idx]);
    float Aim = A_imag[idx];
    float er  = expf(Are*dt);
    float rr  = er*cosf(Aim*dt), ri = er*sinf(Aim*dt);
    float nre = rr - 1.f, nim = ri;
    float den = Are*Are + Aim*Aim;
    float qre = (nre*Are + nim*Aim)/den;
    float qim = (nim*Are - nre*Aim)/den;
    float Cre = C[2*idx], Cim = C[2*idx+1];
    g_rr[idx] = rr;  g_ri[idx] = ri;
    g_cr[idx] = 2.f*(Cre*qre - Cim*qim);
    g_ci[idx] = -2.f*(Cre*qim + Cim*qre);
}

// W -> fp16 copy
__global__ void wcvt_kernel(const float* __restrict__ Wm) {
    int i = blockIdx.x*blockDim.x + threadIdx.x;
    g_wh[i] = __float2half_rn(Wm[i]);
}

// ---------------- K1: LayerNorm over H, warp per (l,b), float4 -------------
__global__ void ln_kernel(const float* __restrict__ u, const float* __restrict__ lnw,
                          const float* __restrict__ lnb) {
    int warp = (blockIdx.x*blockDim.x + threadIdx.x) >> 5;
    int lane = threadIdx.x & 31;
    const float4* row = (const float4*)(u + (size_t)warp*H_DIM);
    float4 v[4];
    float s = 0.f, sq = 0.f;
    #pragma unroll
    for (int i = 0; i < 4; i++) {
        float4 x = row[lane + i*32];
        v[i] = x;
        s  += x.x + x.y + x.z + x.w;
        sq += x.x*x.x + x.y*x.y + x.z*x.z + x.w*x.w;
    }
    #pragma unroll
    for (int o = 16; o >= 1; o >>= 1) {
        s  += __shfl_xor_sync(0xffffffffu, s,  o);
        sq += __shfl_xor_sync(0xffffffffu, sq, o);
    }
    float mu = s*(1.f/H_DIM);
    float rstd = rsqrtf(sq*(1.f/H_DIM) - mu*mu + 1e-5f);
    float4* orow = (float4*)(g_un + (size_t)warp*H_DIM);
    const float4* w4 = (const float4*)lnw;
    const float4* b4 = (const float4*)lnb;
    #pragma unroll
    for (int i = 0; i < 4; i++) {
        int c = lane + i*32;
        float4 wv = w4[c], bv = b4[c], o;
        o.x = (v[i].x - mu)*rstd*wv.x + bv.x;
        o.y = (v[i].y - mu)*rstd*wv.y + bv.y;
        o.z = (v[i].z - mu)*rstd*wv.z + bv.z;
        o.w = (v[i].w - mu)*rstd*wv.w + bv.w;
        orow[c] = o;
    }
}

// ---------------- K2: packed f32x2 scan, 2 h per warp -----------------------
// Block 128 thr = 4 warps = 8 h of one b. Warp w owns h pair (h0+2w, h0+2w+1);
// lane n holds state n of both h packed in one f32x2 pair. All recurrence math
// is element-wise in the pair -> fma.rn.f32x2 (FFMA2) halves FMA issue per h.
// Reduce: packed rows vs[t][lane] (f32x2), lane t reads 16xLDS.128 (stride 68
// words -> conflict-free) and tree-adds with add.rn.f32x2.
#define VSTR 68
__global__ void __launch_bounds__(128) scan_kernel(const float* __restrict__ D) {
    __shared__ float us2[8][34];
    __shared__ float ys[32][9];
    __shared__ float vs[4][32*VSTR];
    int tid = threadIdx.x, w = tid >> 5, lane = tid & 31;
    int h0 = blockIdx.x*8, b = blockIdx.y;
    int ha = h0 + 2*w, hb = ha + 1;
    // scalar coefficients for both h, then pack
    float rra = g_rr[ha*NS+lane], rrb = g_rr[hb*NS+lane];
    float ria = g_ri[ha*NS+lane], rib = g_ri[hb*NS+lane];
    float cra = g_cr[ha*NS+lane], crb = g_cr[hb*NS+lane];
    float cia = g_ci[ha*NS+lane], cib = g_ci[hb*NS+lane];
    ull rr   = pk(rra, rrb);
    ull ri   = pk(ria, rib);
    ull cr   = pk(cra, crb);
    ull ci   = pk(cia, cib);
    ull rr2  = pk(rra*rra - ria*ria, rrb*rrb - rib*rib);
    ull ri2  = pk(2.f*rra*ria,       2.f*rrb*rib);
    ull nri2 = pk(-2.f*rra*ria,     -2.f*rrb*rib);
    ull cr1  = pk(cra*rra + cia*ria, crb*rrb + cib*rib);
    ull ci1  = pk(cia*rra - cra*ria, cib*rrb - crb*rib);
    float Da = D[ha], Db = D[hb];
    ull sre = 0, sim = 0;                 // packed states (0.0f, 0.0f)
    int hloc = tid & 7, tt = tid >> 3;    // fill/store mapping: 8h x 32t
    const float* usrc = g_un + (size_t)b*H_DIM + h0;
    float* vw = vs[w];

    for (int l0 = 0; l0 < L_SEQ; l0 += 32) {
        us2[hloc][tt]      = usrc[(size_t)(l0 + tt)*BH + hloc];
        us2[hloc][tt + 16] = usrc[(size_t)(l0 + tt + 16)*BH + hloc];
        __syncthreads();
        #pragma unroll
        for (int m = 0; m < 16; m++) {
            float2 ua = *(const float2*)&us2[2*w][2*m];       // broadcast LDS.64
            float2 ub = *(const float2*)&us2[2*w+1][2*m];
            ull U0 = pk(ua.x, ub.x), U1 = pk(ua.y, ub.y);
            ull v0  = f2fma(cr1, sre, f2fma(ci1, sim, f2mul(cr, U0)));
            ull nre = f2fma(rr2, sre, f2fma(nri2, sim, f2fma(rr, U0, U1)));
            ull nim = f2fma(rr2, sim, f2fma(ri2, sre, f2mul(ri, U0)));
            sre = nre; sim = nim;
            ull v1  = f2fma(cr, sre, f2mul(ci, sim));
            *(ull*)&vw[(2*m)*VSTR + 2*lane]   = v0;
            *(ull*)&vw[(2*m+1)*VSTR + 2*lane] = v1;
        }
        __syncwarp();
        // lane t: packed sum of row t over 32 states (both h at once)
        const ulonglong2* vr = (const ulonglong2*)(vw + lane*VSTR);
        ulonglong2 q = vr[0];
        ull s0 = q.x, s1 = q.y;
        #pragma unroll
        for (int k = 1; k < 16; k++) {
            q = vr[k];
            s0 = f2add(s0, q.x);
            s1 = f2add(s1, q.y);
        }
        float ya, yb;
        upk(ya, yb, f2add(s0, s1));
        float uca = us2[2*w][lane], ucb = us2[2*w+1][lane];
        float yda = ya + Da*uca, ydb = yb + Db*ucb;
        ys[lane][2*w]   = 0.5f*yda*(1.f + erff(yda*0.70710678118f));
        ys[lane][2*w+1] = 0.5f*ydb*(1.f + erff(ydb*0.70710678118f));
        __syncthreads();
        g_yh[((size_t)b*L_SEQ + l0 + tt)*H_DIM + h0 + hloc]      = __float2half_rn(ys[tt][hloc]);
        g_yh[((size_t)b*L_SEQ + l0 + tt + 16)*H_DIM + h0 + hloc] = __float2half_rn(ys[tt+16][hloc]);
    }
}

// ---------------- K3: mma.sync fp16 GEMM + GLU + residual (R12, ~150us) -----
#define NKT    16
#define NSTG   3
#define T_H    (128*40)
#define SMEM_BYTES (NSTG*2*T_H*2)

__global__ void __launch_bounds__(256, 2) mma_gemm(const float* __restrict__ bconv,
                                                   const float* __restrict__ u,
                                                   float* __restrict__ out) {
    extern __shared__ __half smh[];
    __half* Abuf = smh;
    __half* Bbuf = smh + NSTG*T_H;
    int tid = threadIdx.x;
    int l0 = blockIdx.x*128, h0 = blockIdx.y*64, b = blockIdx.z;
    int wid = tid >> 5, lane = tid & 31;
    int wm = wid & 1, wn = wid >> 1;
    int g = lane >> 2, t = lane & 3;
    const __half* Abase = g_yh + ((size_t)b*L_SEQ + l0)*H_DIM;

    float c[4][4][4];
    #pragma unroll
    for (int i = 0; i < 4; i++)
        #pragma unroll
        for (int j = 0; j < 4; j++)
            #pragma unroll
            for (int q = 0; q < 4; q++) c[i][j][q] = 0.f;

    auto load_stage = [&](int kt, int s) {
        int k0 = kt*32;
        __half* As = Abuf + s*T_H;
        __half* Bs = Bbuf + s*T_H;
        #pragma unroll
        for (int p = 0; p < 2; p++) {
            int idx = tid + p*256;
            int r = idx >> 2, seg = idx & 3;
            const __half* srcA = Abase + (size_t)r*H_DIM + k0 + seg*8;
            uint32_t dstA = smem_u32(As + r*40 + seg*8);
            asm volatile("cp.async.cg.shared.global [%0], [%1], 16;" :: "r"(dstA), "l"(srcA));
            int orow = (r & 1) ? (H_DIM + h0 + (r >> 1)) : (h0 + (r >> 1));
            const __half* srcB = g_wh + (size_t)orow*H_DIM + k0 + seg*8;
            uint32_t dstB = smem_u32(Bs + r*40 + seg*8);
            asm volatile("cp.async.cg.shared.global [%0], [%1], 16;" :: "r"(dstB), "l"(srcB));
        }
    };
    auto compute = [&](int s) {
        const __half* As = Abuf + s*T_H;
        const __half* Bs = Bbuf + s*T_H;
        #pragma unroll
        for (int kk = 0; kk < 32; kk += 16) {
            uint32_t a[4][4], bb[2][4];
            #pragma unroll
            for (int mt = 0; mt < 4; mt++) {
                int row = wm*64 + mt*16 + (lane & 7) + ((lane >> 3) & 1)*8;
                int col = kk + (lane >> 4)*8;
                uint32_t ad = smem_u32(As + row*40 + col);
                asm volatile("ldmatrix.sync.aligned.m8n8.x4.shared.b16 {%0,%1,%2,%3}, [%4];"
                    : "=r"(a[mt][0]), "=r"(a[mt][1]), "=r"(a[mt][2]), "=r"(a[mt][3]) : "r"(ad));
            }
            #pragma unroll
            for (int ntp = 0; ntp < 2; ntp++) {
                int row = wn*32 + ntp*16 + (lane & 7) + ((lane >= 16) ? 8 : 0);
                int col = kk + ((lane >> 3) & 1)*8;
                uint32_t ad = smem_u32(Bs + row*40 + col);
                asm volatile("ldmatrix.sync.aligned.m8n8.x4.shared.b16 {%0,%1,%2,%3}, [%4];"
                    : "=r"(bb[ntp][0]), "=r"(bb[ntp][1]), "=r"(bb[ntp][2]), "=r"(bb[ntp][3]) : "r"(ad));
            }
            #pragma unroll
            for (int mt = 0; mt < 4; mt++)
                #pragma unroll
                for (int nt = 0; nt < 4; nt++) {
                    int ntp = nt >> 1, hh = nt & 1;
                    asm volatile(
                        "mma.sync.aligned.m16n8k16.row.col.f32.f16.f16.f32 "
                        "{%0,%1,%2,%3}, {%4,%5,%6,%7}, {%8,%9}, {%0,%1,%2,%3};"
                        : "+f"(c[mt][nt][0]), "+f"(c[mt][nt][1]),
                          "+f"(c[mt][nt][2]), "+f"(c[mt][nt][3])
                        : "r"(a[mt][0]), "r"(a[mt][1]), "r"(a[mt][2]), "r"(a[mt][3]),
                          "r"(bb[ntp][hh*2]), "r"(bb[ntp][hh*2+1]));
                }
        }
    };

    load_stage(0, 0);
    asm volatile("cp.async.commit_group;");
    load_stage(1, 1);
    asm volatile("cp.async.commit_group;");
    int sidx = 0, lidx = 2;
    for (int kt = 0; kt < NKT; kt++) {
        asm volatile("cp.async.wait_group 1;");
        __syncthreads();
        if (kt + 2 < NKT) load_stage(kt + 2, lidx);
        asm volatile("cp.async.commit_group;");
        compute(sidx);
        if (++sidx == NSTG) sidx = 0;
        if (++lidx == NSTG) lidx = 0;
    }

    #pragma unroll
    for (int mt = 0; mt < 4; mt++) {
        #pragma unroll
        for (int nt = 0; nt < 4; nt++) {
            int h = h0 + wn*16 + nt*4 + t;
            float bA = bconv[h], bG = bconv[H_DIM + h];
            #pragma unroll
            for (int r2 = 0; r2 < 2; r2++) {
                int l = l0 + wm*64 + mt*16 + g + r2*8;
                float av = c[mt][nt][r2*2+0] + bA;
                float gv = c[mt][nt][r2*2+1] + bG;
                size_t o = (size_t)l*BH + (size_t)b*H_DIM + h;
                out[o] = u[o] + av * (1.f/(1.f + __expf(-gv)));
            }
        }
    }
}

// ---------------------------------------------------------------------------
extern "C" void kernel_launch(void* const* d_in, const int* in_sizes, int n_in,
                              void* d_out, int out_size) {
    const float* u          = (const float*)d_in[0];
    const float* log_dt     = (const float*)d_in[1];
    const float* C          = (const float*)d_in[2];
    const float* log_A_real = (const float*)d_in[3];
    const float* A_imag     = (const float*)d_in[4];
    const float* D          = (const float*)d_in[5];
    const float* Wm         = (const float*)d_in[6];
    const float* b_conv     = (const float*)d_in[7];
    const float* ln_w       = (const float*)d_in[8];
    const float* ln_b       = (const float*)d_in[9];
    float* out = (float*)d_out;

    cudaFuncSetAttribute(mma_gemm, cudaFuncAttributeMaxDynamicSharedMemorySize, SMEM_BYTES);

    const_kernel<<<64, 256>>>(log_dt, C, log_A_real, A_imag);
    wcvt_kernel<<<512, 1024>>>(Wm);
    ln_kernel<<<(L_SEQ*B_SZ)/8, 256>>>(u, ln_w, ln_b);
    scan_kernel<<<dim3(H_DIM/8, B_SZ), 128>>>(D);
    mma_gemm<<<dim3(L_SEQ/128, H_DIM/64, B_SZ), 256, SMEM_BYTES>>>(b_conv, u, out);
}

// round 15
// speedup vs baseline: 1.2073x; 1.2073x over previous
#include <cuda_runtime.h>
#include <cuda_fp16.h>
#include <math.h>
#include <stdint.h>

#define L_SEQ 2048
#define B_SZ  16
#define H_DIM 512
#define NS    32
#define BH    (B_SZ*H_DIM)
#define LBH   (L_SEQ*B_SZ*H_DIM)

__device__ float  g_un[LBH];              // LN output, (L,B,H) fp32
__device__ __half g_ut[LBH];              // LN output, (B,H,L) fp16
__device__ __half g_yhl[LBH];             // gelu out, (B,H,L) fp16
__device__ __half g_yh[LBH];              // gelu out, (B,L,H) fp16 (GEMM A)
__device__ __half g_wh[2*H_DIM*H_DIM];    // W conv, fp16
__device__ float g_rr[H_DIM*NS], g_ri[H_DIM*NS], g_cr[H_DIM*NS], g_ci[H_DIM*NS];
__device__ __half g_M[H_DIM*32*96];       // per-h [T(32x32) | P(32x64)]
__device__ __half g_Wm[H_DIM*64*32];      // per-h state-hop matrix
__device__ float  g_r32[H_DIM*NS*2];      // per-(h,n) r^32

__device__ __forceinline__ uint32_t smem_u32(const void* p) {
    uint32_t a;
    asm("{ .reg .u64 t; cvta.to.shared.u64 t, %1; cvt.u32.u64 %0, t; }" : "=r"(a) : "l"(p));
    return a;
}
#define LDM_X4(r0,r1,r2,r3,addr) \
    asm volatile("ldmatrix.sync.aligned.m8n8.x4.shared.b16 {%0,%1,%2,%3}, [%4];" \
        : "=r"(r0), "=r"(r1), "=r"(r2), "=r"(r3) : "r"(addr))
#define MMA16816(c0,c1,c2,c3,a0,a1,a2,a3,b0,b1) \
    asm volatile("mma.sync.aligned.m16n8k16.row.col.f32.f16.f16.f32 " \
        "{%0,%1,%2,%3}, {%4,%5,%6,%7}, {%8,%9}, {%0,%1,%2,%3};" \
        : "+f"(c0), "+f"(c1), "+f"(c2), "+f"(c3) \
        : "r"(a0), "r"(a1), "r"(a2), "r"(a3), "r"(b0), "r"(b1))

// ---------------- K0: SSM constants ----------------
__global__ void const_kernel(const float* __restrict__ log_dt, const float* __restrict__ C,
                             const float* __restrict__ log_A_real, const float* __restrict__ A_imag) {
    int idx = blockIdx.x*blockDim.x + threadIdx.x;
    if (idx >= H_DIM*NS) return;
    int h = idx >> 5;
    float dt  = expf(log_dt[h]);
    float Are = -expf(log_A_real[idx]);
    float Aim = A_imag[idx];
    float er  = expf(Are*dt);
    float rr  = er*cosf(Aim*dt), ri = er*sinf(Aim*dt);
    float nre = rr - 1.f, nim = ri;
    float den = Are*Are + Aim*Aim;
    float qre = (nre*Are + nim*Aim)/den;
    float qim = (nim*Are - nre*Aim)/den;
    float Cre = C[2*idx], Cim = C[2*idx+1];
    g_rr[idx] = rr;  g_ri[idx] = ri;
    g_cr[idx] = 2.f*(Cre*qre - Cim*qim);
    g_ci[idx] = -2.f*(Cre*qim + Cim*qre);
}

// ---------------- K0b: build per-h T/P/W matrices ---------------------------
__global__ void mat_kernel() {     // grid 512, block 32
    __shared__ float kap[32];
    int h = blockIdx.x, n = threadIdx.x;
    float rr = g_rr[h*NS+n], ri = g_ri[h*NS+n];
    float cr = g_cr[h*NS+n], ci = g_ci[h*NS+n];
    float Rre = 1.f, Rim = 0.f;            // r^0
    __half* Mh = g_M  + h*32*96;
    __half* Wh = g_Wm + h*64*32;
    for (int d = 0; d < 32; d++) {
        float kv = cr*Rre + ci*Rim;        // kappa[d] uses r^d
        #pragma unroll
        for (int o = 16; o >= 1; o >>= 1) kv += __shfl_xor_sync(0xffffffffu, kv, o);
        if (n == 0) kap[d] = kv;
        Wh[(2*n)*32   + (31-d)] = __float2half_rn(Rre);   // W[2n][j]=Re(r^{31-j})
        Wh[(2*n+1)*32 + (31-d)] = __float2half_rn(Rim);
        float nR = Rre*rr - Rim*ri, nI = Rre*ri + Rim*rr;
        Rre = nR; Rim = nI;                // now r^{d+1}
        Mh[d*96 + 32 + 2*n]   = __float2half_rn(cr*Rre + ci*Rim);   // P[t=d]
        Mh[d*96 + 32 + 2*n+1] = __float2half_rn(ci*Rre - cr*Rim);
    }
    g_r32[(h*NS+n)*2]   = Rre;             // r^32
    g_r32[(h*NS+n)*2+1] = Rim;
    __syncwarp();
    for (int j = 0; j < 32; j++)           // T row t=n: kappa[t-j], causal
        Mh[n*96 + j] = (j <= n) ? __float2half_rn(kap[n-j]) : __float2half_rn(0.f);
}

// W conv -> fp16
__global__ void wcvt_kernel(const float* __restrict__ Wm) {
    int i = blockIdx.x*blockDim.x + threadIdx.x;
    g_wh[i] = __float2half_rn(Wm[i]);
}

// ---------------- K1: LayerNorm over H, warp per (l,b) ----------------------
__global__ void ln_kernel(const float* __restrict__ u, const float* __restrict__ lnw,
                          const float* __restrict__ lnb) {
    int warp = (blockIdx.x*blockDim.x + threadIdx.x) >> 5;
    int lane = threadIdx.x & 31;
    const float4* row = (const float4*)(u + (size_t)warp*H_DIM);
    float4 v[4];
    float s = 0.f, sq = 0.f;
    #pragma unroll
    for (int i = 0; i < 4; i++) {
        float4 x = row[lane + i*32];
        v[i] = x;
        s  += x.x + x.y + x.z + x.w;
        sq += x.x*x.x + x.y*x.y + x.z*x.z + x.w*x.w;
    }
    #pragma unroll
    for (int o = 16; o >= 1; o >>= 1) {
        s  += __shfl_xor_sync(0xffffffffu, s,  o);
        sq += __shfl_xor_sync(0xffffffffu, sq, o);
    }
    float mu = s*(1.f/H_DIM);
    float rstd = rsqrtf(sq*(1.f/H_DIM) - mu*mu + 1e-5f);
    float4* orow = (float4*)(g_un + (size_t)warp*H_DIM);
    const float4* w4 = (const float4*)lnw;
    const float4* b4 = (const float4*)lnb;
    #pragma unroll
    for (int i = 0; i < 4; i++) {
        int c = lane + i*32;
        float4 wv = w4[c], bv = b4[c], o;
        o.x = (v[i].x - mu)*rstd*wv.x + bv.x;
        o.y = (v[i].y - mu)*rstd*wv.y + bv.y;
        o.z = (v[i].z - mu)*rstd*wv.z + bv.z;
        o.w = (v[i].w - mu)*rstd*wv.w + bv.w;
        orow[c] = o;
    }
}

// ---------------- T1: (L,B,H) fp32 -> (B,H,L) fp16 --------------------------
__global__ void t1_kernel() {      // grid (64,16,16), block (32,8)
    __shared__ float sm[32][33];
    int l0 = blockIdx.x*32, h0 = blockIdx.y*32, b = blockIdx.z;
    int tx = threadIdx.x, ty = threadIdx.y;
    #pragma unroll
    for (int i = 0; i < 4; i++)
        sm[ty+8*i][tx] = g_un[(size_t)(l0+ty+8*i)*BH + b*H_DIM + h0 + tx];
    __syncthreads();
    #pragma unroll
    for (int i = 0; i < 4; i++)
        g_ut[((size_t)b*H_DIM + h0+ty+8*i)*L_SEQ + l0 + tx] = __float2half_rn(sm[tx][ty+8*i]);
}

// ---------------- T2: (B,H,L) fp16 -> (B,L,H) fp16 --------------------------
__global__ void t2_kernel() {      // grid (64,16,16), block (32,8)
    __shared__ __half sm[32][34];
    int l0 = blockIdx.x*32, h0 = blockIdx.y*32, b = blockIdx.z;
    int tx = threadIdx.x, ty = threadIdx.y;
    #pragma unroll
    for (int i = 0; i < 4; i++)
        sm[ty+8*i][tx] = g_yhl[((size_t)b*H_DIM + h0+ty+8*i)*L_SEQ + l0 + tx];
    __syncthreads();
    #pragma unroll
    for (int i = 0; i < 4; i++)
        g_yh[((size_t)b*L_SEQ + l0+ty+8*i)*H_DIM + h0 + tx] = sm[tx][ty+8*i];
}

// ---------------- K2: fused chunked scan on tensor cores --------------------
// Block = one (h, b). 128 thr = 4 warps; warp w owns chunk cols [16w,16w+16).
// Phase 1: D[64 states][64 ch] = W_h[64x32] @ U^T ; Phase 2 (warp 0): state
// hop s_{c+1}=r32*s_c+d_c, S[ch][64]; Phase 3: Y[32 t][64 ch] = M_h[32x96] @
// [U;S]^T, then D-skip + GELU -> (B,H,L) contiguous.
__global__ void __launch_bounds__(128, 5) scan_mega(const float* __restrict__ Dp) {
    __shared__ __half Us[64][40];          // [chunk][j]
    __shared__ __half Ms[32][104];         // [t][k 0..95]
    __shared__ __half Ws[64][40];          // [2n][j]
    __shared__ __half Ds[64][72];          // [2n][chunk]
    __shared__ __half Ss[64][72];          // [chunk][2n]
    __shared__ __align__(16) __half Ys[2048];
    int h = blockIdx.x, b = blockIdx.y;
    int tid = threadIdx.x, w = tid >> 5, lane = tid & 31;

    {   // stage U (2048 halves), M (3072), W (2048) via 4B words
        const uint32_t* us = (const uint32_t*)(g_ut + ((size_t)b*H_DIM + h)*L_SEQ);
        for (int i = tid; i < 1024; i += 128) {
            int s = i*2, ch = s >> 5, j = s & 31;
            *(uint32_t*)&Us[ch][j] = us[i];
        }
        const uint32_t* ms = (const uint32_t*)(g_M + h*32*96);
        for (int i = tid; i < 1536; i += 128) {
            int s = i*2, r = s/96, cpos = s - r*96;
            *(uint32_t*)&Ms[r][cpos] = ms[i];
        }
        const uint32_t* ws = (const uint32_t*)(g_Wm + h*64*32);
        for (int i = tid; i < 1024; i += 128) {
            int s = i*2, r = s >> 5, cpos = s & 31;
            *(uint32_t*)&Ws[r][cpos] = ws[i];
        }
    }
    __syncthreads();

    int g = lane >> 2, tq = lane & 3;
    {   // Phase 1: D = W @ U^T   (M=64, N=16/warp, K=32)
        float cd[4][2][4];
        #pragma unroll
        for (int i = 0; i < 4; i++)
            #pragma unroll
            for (int j = 0; j < 2; j++)
                #pragma unroll
                for (int q = 0; q < 4; q++) cd[i][j][q] = 0.f;
        #pragma unroll
        for (int ks = 0; ks < 2; ks++) {
            int kk = ks*16;
            uint32_t a[4][4], bb[4];
            #pragma unroll
            for (int mt = 0; mt < 4; mt++) {
                int row = mt*16 + (lane & 7) + ((lane >> 3) & 1)*8;
                int col = kk + (lane >> 4)*8;
                LDM_X4(a[mt][0], a[mt][1], a[mt][2], a[mt][3], smem_u32(&Ws[row][col]));
            }
            {
                int row = w*16 + (lane & 7) + ((lane >= 16) ? 8 : 0);
                int col = kk + ((lane >> 3) & 1)*8;
                LDM_X4(bb[0], bb[1], bb[2], bb[3], smem_u32(&Us[row][col]));
            }
            #pragma unroll
            for (int mt = 0; mt < 4; mt++)
                #pragma unroll
                for (int nt = 0; nt < 2; nt++)
                    MMA16816(cd[mt][nt][0], cd[mt][nt][1], cd[mt][nt][2], cd[mt][nt][3],
                             a[mt][0], a[mt][1], a[mt][2], a[mt][3], bb[nt*2], bb[nt*2+1]);
        }
        #pragma unroll
        for (int mt = 0; mt < 4; mt++)
            #pragma unroll
            for (int nt = 0; nt < 2; nt++)
                #pragma unroll
                for (int q = 0; q < 4; q++) {
                    int row = mt*16 + g + ((q >> 1) ? 8 : 0);
                    int col = w*16 + nt*8 + 2*tq + (q & 1);
                    Ds[row][col] = __float2half_rn(cd[mt][nt][q]);
                }
    }
    __syncthreads();

    if (w == 0) {   // Phase 2: sequential state hop (lane = n)
        int n = lane;
        float r32r = g_r32[(h*NS+n)*2], r32i = g_r32[(h*NS+n)*2+1];
        float sre = 0.f, sim = 0.f;
        for (int c = 0; c < 64; c++) {
            Ss[c][2*n]   = __float2half_rn(sre);
            Ss[c][2*n+1] = __float2half_rn(sim);
            float dre = __half2float(Ds[2*n][c]);
            float dim = __half2float(Ds[2*n+1][c]);
            float nr = fmaf(r32r, sre, fmaf(-r32i, sim, dre));
            float ni = fmaf(r32r, sim, fmaf(r32i, sre, dim));
            sre = nr; sim = ni;
        }
    }
    __syncthreads();

    {   // Phase 3: Y = M @ [U;S]^T  (M=32, N=16/warp, K=96)
        float cy[2][2][4];
        #pragma unroll
        for (int i = 0; i < 2; i++)
            #pragma unroll
            for (int j = 0; j < 2; j++)
                #pragma unroll
                for (int q = 0; q < 4; q++) cy[i][j][q] = 0.f;
        #pragma unroll
        for (int ks = 0; ks < 6; ks++) {
            int kk = ks*16;
            uint32_t a[2][4], bb[4];
            #pragma unroll
            for (int mt = 0; mt < 2; mt++) {
                int row = mt*16 + (lane & 7) + ((lane >> 3) & 1)*8;
                int col = kk + (lane >> 4)*8;
                LDM_X4(a[mt][0], a[mt][1], a[mt][2], a[mt][3], smem_u32(&Ms[row][col]));
            }
            {
                int row = w*16 + (lane & 7) + ((lane >= 16) ? 8 : 0);
                int col = ((lane >> 3) & 1)*8;
                uint32_t ad = (ks < 2) ? smem_u32(&Us[row][kk + col])
                                       : smem_u32(&Ss[row][kk - 32 + col]);
                LDM_X4(bb[0], bb[1], bb[2], bb[3], ad);
            }
            #pragma unroll
            for (int mt = 0; mt < 2; mt++)
                #pragma unroll
                for (int nt = 0; nt < 2; nt++)
                    MMA16816(cy[mt][nt][0], cy[mt][nt][1], cy[mt][nt][2], cy[mt][nt][3],
                             a[mt][0], a[mt][1], a[mt][2], a[mt][3], bb[nt*2], bb[nt*2+1]);
        }
        float Dh = Dp[h];
        #pragma unroll
        for (int mt = 0; mt < 2; mt++)
            #pragma unroll
            for (int nt = 0; nt < 2; nt++)
                #pragma unroll
                for (int q = 0; q < 4; q++) {
                    int trow = mt*16 + g + ((q >> 1) ? 8 : 0);
                    int ch   = w*16 + nt*8 + 2*tq + (q & 1);
                    float uv = __half2float(Us[ch][trow]);
                    float yd = cy[mt][nt][q] + Dh*uv;
                    float ge = 0.5f*yd*(1.f + erff(yd*0.70710678118f));
                    Ys[ch*32 + trow] = __float2half_rn(ge);
                }
    }
    __syncthreads();
    {
        uint32_t* dst = (uint32_t*)(g_yhl + ((size_t)b*H_DIM + h)*L_SEQ);
        const uint32_t* src = (const uint32_t*)Ys;
        for (int i = tid; i < 1024; i += 128) dst[i] = src[i];
    }
}

// ---------------- K3: mma.sync fp16 GEMM + GLU + residual (R12, ~150us) -----
#define NKT    16
#define NSTG   3
#define T_H    (128*40)
#define SMEM_BYTES (NSTG*2*T_H*2)

__global__ void __launch_bounds__(256, 2) mma_gemm(const float* __restrict__ bconv,
                                                   const float* __restrict__ u,
                                                   float* __restrict__ out) {
    extern __shared__ __half smh[];
    __half* Abuf = smh;
    __half* Bbuf = smh + NSTG*T_H;
    int tid = threadIdx.x;
    int l0 = blockIdx.x*128, h0 = blockIdx.y*64, b = blockIdx.z;
    int wid = tid >> 5, lane = tid & 31;
    int wm = wid & 1, wn = wid >> 1;
    int g = lane >> 2, t = lane & 3;
    const __half* Abase = g_yh + ((size_t)b*L_SEQ + l0)*H_DIM;

    float c[4][4][4];
    #pragma unroll
    for (int i = 0; i < 4; i++)
        #pragma unroll
        for (int j = 0; j < 4; j++)
            #pragma unroll
            for (int q = 0; q < 4; q++) c[i][j][q] = 0.f;

    auto load_stage = [&](int kt, int s) {
        int k0 = kt*32;
        __half* As = Abuf + s*T_H;
        __half* Bs = Bbuf + s*T_H;
        #pragma unroll
        for (int p = 0; p < 2; p++) {
            int idx = tid + p*256;
            int r = idx >> 2, seg = idx & 3;
            const __half* srcA = Abase + (size_t)r*H_DIM + k0 + seg*8;
            uint32_t dstA = smem_u32(As + r*40 + seg*8);
            asm volatile("cp.async.cg.shared.global [%0], [%1], 16;" :: "r"(dstA), "l"(srcA));
            int orow = (r & 1) ? (H_DIM + h0 + (r >> 1)) : (h0 + (r >> 1));
            const __half* srcB = g_wh + (size_t)orow*H_DIM + k0 + seg*8;
            uint32_t dstB = smem_u32(Bs + r*40 + seg*8);
            asm volatile("cp.async.cg.shared.global [%0], [%1], 16;" :: "r"(dstB), "l"(srcB));
        }
    };
    auto compute = [&](int s) {
        const __half* As = Abuf + s*T_H;
        const __half* Bs = Bbuf + s*T_H;
        #pragma unroll
        for (int kk = 0; kk < 32; kk += 16) {
            uint32_t a[4][4], bb[2][4];
            #pragma unroll
            for (int mt = 0; mt < 4; mt++) {
                int row = wm*64 + mt*16 + (lane & 7) + ((lane >> 3) & 1)*8;
                int col = kk + (lane >> 4)*8;
                LDM_X4(a[mt][0], a[mt][1], a[mt][2], a[mt][3], smem_u32(As + row*40 + col));
            }
            #pragma unroll
            for (int ntp = 0; ntp < 2; ntp++) {
                int row = wn*32 + ntp*16 + (lane & 7) + ((lane >= 16) ? 8 : 0);
                int col = kk + ((lane >> 3) & 1)*8;
                LDM_X4(bb[ntp][0], bb[ntp][1], bb[ntp][2], bb[ntp][3], smem_u32(Bs + row*40 + col));
            }
            #pragma unroll
            for (int mt = 0; mt < 4; mt++)
                #pragma unroll
                for (int nt = 0; nt < 4; nt++) {
                    int ntp = nt >> 1, hh = nt & 1;
                    MMA16816(c[mt][nt][0], c[mt][nt][1], c[mt][nt][2], c[mt][nt][3],
                             a[mt][0], a[mt][1], a[mt][2], a[mt][3],
                             bb[ntp][hh*2], bb[ntp][hh*2+1]);
                }
        }
    };

    load_stage(0, 0);
    asm volatile("cp.async.commit_group;");
    load_stage(1, 1);
    asm volatile("cp.async.commit_group;");
    int sidx = 0, lidx = 2;
    for (int kt = 0; kt < NKT; kt++) {
        asm volatile("cp.async.wait_group 1;");
        __syncthreads();
        if (kt + 2 < NKT) load_stage(kt + 2, lidx);
        asm volatile("cp.async.commit_group;");
        compute(sidx);
        if (++sidx == NSTG) sidx = 0;
        if (++lidx == NSTG) lidx = 0;
    }

    #pragma unroll
    for (int mt = 0; mt < 4; mt++) {
        #pragma unroll
        for (int nt = 0; nt < 4; nt++) {
            int h = h0 + wn*16 + nt*4 + t;
            float bA = bconv[h], bG = bconv[H_DIM + h];
            #pragma unroll
            for (int r2 = 0; r2 < 2; r2++) {
                int l = l0 + wm*64 + mt*16 + g + r2*8;
                float av = c[mt][nt][r2*2+0] + bA;
                float gv = c[mt][nt][r2*2+1] + bG;
                size_t o = (size_t)l*BH + (size_t)b*H_DIM + h;
                out[o] = u[o] + av * (1.f/(1.f + __expf(-gv)));
            }
        }
    }
}

// ---------------------------------------------------------------------------
extern "C" void kernel_launch(void* const* d_in, const int* in_sizes, int n_in,
                              void* d_out, int out_size) {
    const float* u          = (const float*)d_in[0];
    const float* log_dt     = (const float*)d_in[1];
    const float* C          = (const float*)d_in[2];
    const float* log_A_real = (const float*)d_in[3];
    const float* A_imag     = (const float*)d_in[4];
    const float* D          = (const float*)d_in[5];
    const float* Wm         = (const float*)d_in[6];
    const float* b_conv     = (const float*)d_in[7];
    const float* ln_w       = (const float*)d_in[8];
    const float* ln_b       = (const float*)d_in[9];
    float* out = (float*)d_out;

    cudaFuncSetAttribute(mma_gemm, cudaFuncAttributeMaxDynamicSharedMemorySize, SMEM_BYTES);

    const_kernel<<<64, 256>>>(log_dt, C, log_A_real, A_imag);
    mat_kernel<<<512, 32>>>();
    wcvt_kernel<<<512, 1024>>>(Wm);
    ln_kernel<<<(L_SEQ*B_SZ)/8, 256>>>(u, ln_w, ln_b);
    t1_kernel<<<dim3(64, 16, 16), dim3(32, 8)>>>();
    scan_mega<<<dim3(H_DIM, B_SZ), 128>>>(D);
    t2_kernel<<<dim3(64, 16, 16), dim3(32, 8)>>>();
    mma_gemm<<<dim3(L_SEQ/128, H_DIM/64, B_SZ), 256, SMEM_BYTES>>>(b_conv, u, out);
}

// round 16
// speedup vs baseline: 1.4747x; 1.2215x over previous
#include <cuda_runtime.h>
#include <cuda_fp16.h>
#include <math.h>
#include <stdint.h>

#define L_SEQ 2048
#define B_SZ  16
#define H_DIM 512
#define NS    32
#define BH    (B_SZ*H_DIM)
#define LBH   (L_SEQ*B_SZ*H_DIM)

__device__ __half g_unh[LBH];             // LN output, (L,B,H) fp16
__device__ __half g_ut[LBH];              // LN output, (B,H,L) fp16
__device__ __half g_yhl[LBH];             // gelu out, (B,H,L) fp16 (GEMM A, k-major rows)
__device__ __half g_wh[2*H_DIM*H_DIM];    // W conv, fp16
__device__ float g_rr[H_DIM*NS], g_ri[H_DIM*NS], g_cr[H_DIM*NS], g_ci[H_DIM*NS];
__device__ __half g_M[H_DIM*32*96];       // per-h [T(32x32) | P(32x64)]
__device__ __half g_Wm[H_DIM*64*32];      // per-h state-hop matrix
__device__ float  g_r32[H_DIM*NS*2];      // per-(h,n) r^32

__device__ __forceinline__ uint32_t smem_u32(const void* p) {
    uint32_t a;
    asm("{ .reg .u64 t; cvta.to.shared.u64 t, %1; cvt.u32.u64 %0, t; }" : "=r"(a) : "l"(p));
    return a;
}
#define LDM_X4(r0,r1,r2,r3,addr) \
    asm volatile("ldmatrix.sync.aligned.m8n8.x4.shared.b16 {%0,%1,%2,%3}, [%4];" \
        : "=r"(r0), "=r"(r1), "=r"(r2), "=r"(r3) : "r"(addr))
#define LDM_X4_T(r0,r1,r2,r3,addr) \
    asm volatile("ldmatrix.sync.aligned.m8n8.x4.trans.shared.b16 {%0,%1,%2,%3}, [%4];" \
        : "=r"(r0), "=r"(r1), "=r"(r2), "=r"(r3) : "r"(addr))
#define MMA16816(c0,c1,c2,c3,a0,a1,a2,a3,b0,b1) \
    asm volatile("mma.sync.aligned.m16n8k16.row.col.f32.f16.f16.f32 " \
        "{%0,%1,%2,%3}, {%4,%5,%6,%7}, {%8,%9}, {%0,%1,%2,%3};" \
        : "+f"(c0), "+f"(c1), "+f"(c2), "+f"(c3) \
        : "r"(a0), "r"(a1), "r"(a2), "r"(a3), "r"(b0), "r"(b1))

// ---------------- K0: SSM constants ----------------
__global__ void const_kernel(const float* __restrict__ log_dt, const float* __restrict__ C,
                             const float* __restrict__ log_A_real, const float* __restrict__ A_imag) {
    int idx = blockIdx.x*blockDim.x + threadIdx.x;
    if (idx >= H_DIM*NS) return;
    int h = idx >> 5;
    float dt  = expf(log_dt[h]);
    float Are = -expf(log_A_real[idx]);
    float Aim = A_imag[idx];
    float er  = expf(Are*dt);
    float rr  = er*cosf(Aim*dt), ri = er*sinf(Aim*dt);
    float nre = rr - 1.f, nim = ri;
    float den = Are*Are + Aim*Aim;
    float qre = (nre*Are + nim*Aim)/den;
    float qim = (nim*Are - nre*Aim)/den;
    float Cre = C[2*idx], Cim = C[2*idx+1];
    g_rr[idx] = rr;  g_ri[idx] = ri;
    g_cr[idx] = 2.f*(Cre*qre - Cim*qim);
    g_ci[idx] = -2.f*(Cre*qim + Cim*qre);
}

// ---------------- K0b: build per-h T/P/W matrices ---------------------------
__global__ void mat_kernel() {     // grid 512, block 32
    __shared__ float kap[32];
    int h = blockIdx.x, n = threadIdx.x;
    float rr = g_rr[h*NS+n], ri = g_ri[h*NS+n];
    float cr = g_cr[h*NS+n], ci = g_ci[h*NS+n];
    float Rre = 1.f, Rim = 0.f;            // r^0
    __half* Mh = g_M  + h*32*96;
    __half* Wh = g_Wm + h*64*32;
    for (int d = 0; d < 32; d++) {
        float kv = cr*Rre + ci*Rim;        // kappa[d] uses r^d
        #pragma unroll
        for (int o = 16; o >= 1; o >>= 1) kv += __shfl_xor_sync(0xffffffffu, kv, o);
        if (n == 0) kap[d] = kv;
        Wh[(2*n)*32   + (31-d)] = __float2half_rn(Rre);
        Wh[(2*n+1)*32 + (31-d)] = __float2half_rn(Rim);
        float nR = Rre*rr - Rim*ri, nI = Rre*ri + Rim*rr;
        Rre = nR; Rim = nI;                // now r^{d+1}
        Mh[d*96 + 32 + 2*n]   = __float2half_rn(cr*Rre + ci*Rim);   // P[t=d]
        Mh[d*96 + 32 + 2*n+1] = __float2half_rn(ci*Rre - cr*Rim);
    }
    g_r32[(h*NS+n)*2]   = Rre;
    g_r32[(h*NS+n)*2+1] = Rim;
    __syncwarp();
    for (int j = 0; j < 32; j++)
        Mh[n*96 + j] = (j <= n) ? __float2half_rn(kap[n-j]) : __float2half_rn(0.f);
}

// W conv -> fp16
__global__ void wcvt_kernel(const float* __restrict__ Wm) {
    int i = blockIdx.x*blockDim.x + threadIdx.x;
    g_wh[i] = __float2half_rn(Wm[i]);
}

// ---------------- K1: LayerNorm over H, fp16 out ----------------------------
__global__ void ln_kernel(const float* __restrict__ u, const float* __restrict__ lnw,
                          const float* __restrict__ lnb) {
    int warp = (blockIdx.x*blockDim.x + threadIdx.x) >> 5;
    int lane = threadIdx.x & 31;
    const float4* row = (const float4*)(u + (size_t)warp*H_DIM);
    float4 v[4];
    float s = 0.f, sq = 0.f;
    #pragma unroll
    for (int i = 0; i < 4; i++) {
        float4 x = row[lane + i*32];
        v[i] = x;
        s  += x.x + x.y + x.z + x.w;
        sq += x.x*x.x + x.y*x.y + x.z*x.z + x.w*x.w;
    }
    #pragma unroll
    for (int o = 16; o >= 1; o >>= 1) {
        s  += __shfl_xor_sync(0xffffffffu, s,  o);
        sq += __shfl_xor_sync(0xffffffffu, sq, o);
    }
    float mu = s*(1.f/H_DIM);
    float rstd = rsqrtf(sq*(1.f/H_DIM) - mu*mu + 1e-5f);
    const float4* w4 = (const float4*)lnw;
    const float4* b4 = (const float4*)lnb;
    __half* orow = g_unh + (size_t)warp*H_DIM;
    #pragma unroll
    for (int i = 0; i < 4; i++) {
        int c = lane + i*32;
        float4 wv = w4[c], bv = b4[c];
        __half2 p0 = __floats2half2_rn((v[i].x - mu)*rstd*wv.x + bv.x,
                                       (v[i].y - mu)*rstd*wv.y + bv.y);
        __half2 p1 = __floats2half2_rn((v[i].z - mu)*rstd*wv.z + bv.z,
                                       (v[i].w - mu)*rstd*wv.w + bv.w);
        uint2 val;
        val.x = *(uint32_t*)&p0; val.y = *(uint32_t*)&p1;
        *(uint2*)(orow + 4*c) = val;
    }
}

// ---------------- T1: (L,B,H) fp16 -> (B,H,L) fp16 --------------------------
__global__ void t1_kernel() {      // grid (64,16,16), block (32,8)
    __shared__ __half sm[32][34];
    int l0 = blockIdx.x*32, h0 = blockIdx.y*32, b = blockIdx.z;
    int tx = threadIdx.x, ty = threadIdx.y;
    #pragma unroll
    for (int i = 0; i < 4; i++)
        sm[ty+8*i][tx] = g_unh[(size_t)(l0+ty+8*i)*BH + b*H_DIM + h0 + tx];
    __syncthreads();
    #pragma unroll
    for (int i = 0; i < 4; i++)
        g_ut[((size_t)b*H_DIM + h0+ty+8*i)*L_SEQ + l0 + tx] = sm[tx][ty+8*i];
}

// ---------------- K2: fused chunked scan on tensor cores --------------------
// Block = one h, FOUR b (M/W staged once). 128 thr = 4 warps.
__global__ void __launch_bounds__(128, 5) scan_mega(const float* __restrict__ Dp) {
    __shared__ __half Us[64][40];          // [chunk][j]
    __shared__ __half Ms[32][104];         // [t][k 0..95]
    __shared__ __half Ws[64][40];          // [2n][j]
    __shared__ __half Ds[64][72];          // [2n][chunk]
    __shared__ __half Ss[64][72];          // [chunk][2n]
    __shared__ __align__(16) __half Ys[2048];
    int h = blockIdx.x;
    int tid = threadIdx.x, w = tid >> 5, lane = tid & 31;
    int g = lane >> 2, tq = lane & 3;
    float Dh = Dp[h];

    {   // stage M (3072 halves), W (2048) once
        const uint32_t* ms = (const uint32_t*)(g_M + h*32*96);
        for (int i = tid; i < 1536; i += 128) {
            int s = i*2, r = s/96, cpos = s - r*96;
            *(uint32_t*)&Ms[r][cpos] = ms[i];
        }
        const uint32_t* ws = (const uint32_t*)(g_Wm + h*64*32);
        for (int i = tid; i < 1024; i += 128) {
            int s = i*2, r = s >> 5, cpos = s & 31;
            *(uint32_t*)&Ws[r][cpos] = ws[i];
        }
    }

    for (int ib = 0; ib < 4; ib++) {
        int b = blockIdx.y*4 + ib;
        {   // stage U (2048 halves)
            const uint32_t* us = (const uint32_t*)(g_ut + ((size_t)b*H_DIM + h)*L_SEQ);
            for (int i = tid; i < 1024; i += 128) {
                int s = i*2, ch = s >> 5, j = s & 31;
                *(uint32_t*)&Us[ch][j] = us[i];
            }
        }
        __syncthreads();

        {   // Phase 1: D = W @ U^T   (M=64, N=16/warp, K=32)
            float cd[4][2][4];
            #pragma unroll
            for (int i = 0; i < 4; i++)
                #pragma unroll
                for (int j = 0; j < 2; j++)
                    #pragma unroll
                    for (int q = 0; q < 4; q++) cd[i][j][q] = 0.f;
            #pragma unroll
            for (int ks = 0; ks < 2; ks++) {
                int kk = ks*16;
                uint32_t a[4][4], bb[4];
                #pragma unroll
                for (int mt = 0; mt < 4; mt++) {
                    int row = mt*16 + (lane & 7) + ((lane >> 3) & 1)*8;
                    int col = kk + (lane >> 4)*8;
                    LDM_X4(a[mt][0], a[mt][1], a[mt][2], a[mt][3], smem_u32(&Ws[row][col]));
                }
                {
                    int row = w*16 + (lane & 7) + ((lane >= 16) ? 8 : 0);
                    int col = kk + ((lane >> 3) & 1)*8;
                    LDM_X4(bb[0], bb[1], bb[2], bb[3], smem_u32(&Us[row][col]));
                }
                #pragma unroll
                for (int mt = 0; mt < 4; mt++)
                    #pragma unroll
                    for (int nt = 0; nt < 2; nt++)
                        MMA16816(cd[mt][nt][0], cd[mt][nt][1], cd[mt][nt][2], cd[mt][nt][3],
                                 a[mt][0], a[mt][1], a[mt][2], a[mt][3], bb[nt*2], bb[nt*2+1]);
            }
            #pragma unroll
            for (int mt = 0; mt < 4; mt++)
                #pragma unroll
                for (int nt = 0; nt < 2; nt++)
                    #pragma unroll
                    for (int q = 0; q < 4; q++) {
                        int row = mt*16 + g + ((q >> 1) ? 8 : 0);
                        int col = w*16 + nt*8 + 2*tq + (q & 1);
                        Ds[row][col] = __float2half_rn(cd[mt][nt][q]);
                    }
        }
        __syncthreads();

        if (w == 0) {   // Phase 2: sequential state hop (lane = n)
            int n = lane;
            float r32r = g_r32[(h*NS+n)*2], r32i = g_r32[(h*NS+n)*2+1];
            float sre = 0.f, sim = 0.f;
            for (int c = 0; c < 64; c++) {
                Ss[c][2*n]   = __float2half_rn(sre);
                Ss[c][2*n+1] = __float2half_rn(sim);
                float dre = __half2float(Ds[2*n][c]);
                float dim = __half2float(Ds[2*n+1][c]);
                float nr = fmaf(r32r, sre, fmaf(-r32i, sim, dre));
                float ni = fmaf(r32r, sim, fmaf(r32i, sre, dim));
                sre = nr; sim = ni;
            }
        }
        __syncthreads();

        {   // Phase 3: Y = M @ [U;S]^T  (M=32, N=16/warp, K=96)
            float cy[2][2][4];
            #pragma unroll
            for (int i = 0; i < 2; i++)
                #pragma unroll
                for (int j = 0; j < 2; j++)
                    #pragma unroll
                    for (int q = 0; q < 4; q++) cy[i][j][q] = 0.f;
            #pragma unroll
            for (int ks = 0; ks < 6; ks++) {
                int kk = ks*16;
                uint32_t a[2][4], bb[4];
                #pragma unroll
                for (int mt = 0; mt < 2; mt++) {
                    int row = mt*16 + (lane & 7) + ((lane >> 3) & 1)*8;
                    int col = kk + (lane >> 4)*8;
                    LDM_X4(a[mt][0], a[mt][1], a[mt][2], a[mt][3], smem_u32(&Ms[row][col]));
                }
                {
                    int row = w*16 + (lane & 7) + ((lane >= 16) ? 8 : 0);
                    int col = ((lane >> 3) & 1)*8;
                    uint32_t ad = (ks < 2) ? smem_u32(&Us[row][kk + col])
                                           : smem_u32(&Ss[row][kk - 32 + col]);
                    LDM_X4(bb[0], bb[1], bb[2], bb[3], ad);
                }
                #pragma unroll
                for (int mt = 0; mt < 2; mt++)
                    #pragma unroll
                    for (int nt = 0; nt < 2; nt++)
                        MMA16816(cy[mt][nt][0], cy[mt][nt][1], cy[mt][nt][2], cy[mt][nt][3],
                                 a[mt][0], a[mt][1], a[mt][2], a[mt][3], bb[nt*2], bb[nt*2+1]);
            }
            #pragma unroll
            for (int mt = 0; mt < 2; mt++)
                #pragma unroll
                for (int nt = 0; nt < 2; nt++)
                    #pragma unroll
                    for (int q = 0; q < 4; q++) {
                        int trow = mt*16 + g + ((q >> 1) ? 8 : 0);
                        int ch   = w*16 + nt*8 + 2*tq + (q & 1);
                        float uv = __half2float(Us[ch][trow]);
                        float yd = cy[mt][nt][q] + Dh*uv;
                        float ge = 0.5f*yd*(1.f + erff(yd*0.70710678118f));
                        Ys[ch*32 + trow] = __float2half_rn(ge);
                    }
        }
        __syncthreads();
        {
            uint32_t* dst = (uint32_t*)(g_yhl + ((size_t)b*H_DIM + h)*L_SEQ);
            const uint32_t* src = (const uint32_t*)Ys;
            for (int i = tid; i < 1024; i += 128) dst[i] = src[i];
        }
    }
}

// ---------------- K3: mma.sync fp16 GEMM + GLU + residual -------------------
// A read directly from g_yhl (B,H,L): smem As[k(32)][l(128)+8], fragments via
// ldmatrix.x4.trans (k-bit and l-bit swap roles vs non-trans). B unchanged.
#define NKT    16
#define NSTG   3
#define A_H    (32*136)
#define B_H    (128*40)
#define SMEM_BYTES (NSTG*(A_H + B_H)*2)

__global__ void __launch_bounds__(256, 2) mma_gemm(const float* __restrict__ bconv,
                                                   const float* __restrict__ u,
                                                   float* __restrict__ out) {
    extern __shared__ __half smh[];
    __half* Abuf = smh;
    __half* Bbuf = smh + NSTG*A_H;
    int tid = threadIdx.x;
    int l0 = blockIdx.x*128, h0 = blockIdx.y*64, b = blockIdx.z;
    int wid = tid >> 5, lane = tid & 31;
    int wm = wid & 1, wn = wid >> 1;
    int g = lane >> 2, t = lane & 3;
    const __half* Abase = g_yhl + (size_t)b*H_DIM*L_SEQ + l0;   // row k, col l

    float c[4][4][4];
    #pragma unroll
    for (int i = 0; i < 4; i++)
        #pragma unroll
        for (int j = 0; j < 4; j++)
            #pragma unroll
            for (int q = 0; q < 4; q++) c[i][j][q] = 0.f;

    auto load_stage = [&](int kt, int s) {
        int k0 = kt*32;
        __half* As = Abuf + s*A_H;
        __half* Bs = Bbuf + s*B_H;
        #pragma unroll
        for (int p = 0; p < 2; p++) {       // A: 32 k-rows x 128 l = 512 x 16B
            int idx = tid + p*256;
            int r = idx >> 4, seg = idx & 15;
            const __half* srcA = Abase + (size_t)(k0 + r)*L_SEQ + seg*8;
            uint32_t dstA = smem_u32(As + r*136 + seg*8);
            asm volatile("cp.async.cg.shared.global [%0], [%1], 16;" :: "r"(dstA), "l"(srcA));
        }
        #pragma unroll
        for (int p = 0; p < 2; p++) {       // B: 128 o-rows x 32 k = 512 x 16B
            int idx = tid + p*256;
            int r = idx >> 2, seg = idx & 3;
            int orow = (r & 1) ? (H_DIM + h0 + (r >> 1)) : (h0 + (r >> 1));
            const __half* srcB = g_wh + (size_t)orow*H_DIM + k0 + seg*8;
            uint32_t dstB = smem_u32(Bs + r*40 + seg*8);
            asm volatile("cp.async.cg.shared.global [%0], [%1], 16;" :: "r"(dstB), "l"(srcB));
        }
    };
    auto compute = [&](int s) {
        const __half* As = Abuf + s*A_H;
        const __half* Bs = Bbuf + s*B_H;
        #pragma unroll
        for (int kk = 0; kk < 32; kk += 16) {
            uint32_t a[4][4], bb[2][4];
            #pragma unroll
            for (int mt = 0; mt < 4; mt++) {   // A via trans: addr row = k, col = l
                int kr = kk + (lane & 7) + ((lane >> 4) & 1)*8;
                int lc = wm*64 + mt*16 + ((lane >> 3) & 1)*8;
                LDM_X4_T(a[mt][0], a[mt][1], a[mt][2], a[mt][3], smem_u32(As + kr*136 + lc));
            }
            #pragma unroll
            for (int ntp = 0; ntp < 2; ntp++) {
                int row = wn*32 + ntp*16 + (lane & 7) + ((lane >= 16) ? 8 : 0);
                int col = kk + ((lane >> 3) & 1)*8;
                LDM_X4(bb[ntp][0], bb[ntp][1], bb[ntp][2], bb[ntp][3], smem_u32(Bs + row*40 + col));
            }
            #pragma unroll
            for (int mt = 0; mt < 4; mt++)
                #pragma unroll
                for (int nt = 0; nt < 4; nt++) {
                    int ntp = nt >> 1, hh = nt & 1;
                    MMA16816(c[mt][nt][0], c[mt][nt][1], c[mt][nt][2], c[mt][nt][3],
                             a[mt][0], a[mt][1], a[mt][2], a[mt][3],
                             bb[ntp][hh*2], bb[ntp][hh*2+1]);
                }
        }
    };

    load_stage(0, 0);
    asm volatile("cp.async.commit_group;");
    load_stage(1, 1);
    asm volatile("cp.async.commit_group;");
    int sidx = 0, lidx = 2;
    for (int kt = 0; kt < NKT; kt++) {
        asm volatile("cp.async.wait_group 1;");
        __syncthreads();
        if (kt + 2 < NKT) load_stage(kt + 2, lidx);
        asm volatile("cp.async.commit_group;");
        compute(sidx);
        if (++sidx == NSTG) sidx = 0;
        if (++lidx == NSTG) lidx = 0;
    }

    #pragma unroll
    for (int mt = 0; mt < 4; mt++) {
        #pragma unroll
        for (int nt = 0; nt < 4; nt++) {
            int h = h0 + wn*16 + nt*4 + t;
            float bA = bconv[h], bG = bconv[H_DIM + h];
            #pragma unroll
            for (int r2 = 0; r2 < 2; r2++) {
                int l = l0 + wm*64 + mt*16 + g + r2*8;
                float av = c[mt][nt][r2*2+0] + bA;
                float gv = c[mt][nt][r2*2+1] + bG;
                size_t o = (size_t)l*BH + (size_t)b*H_DIM + h;
                out[o] = u[o] + av * (1.f/(1.f + __expf(-gv)));
            }
        }
    }
}

// ---------------------------------------------------------------------------
extern "C" void kernel_launch(void* const* d_in, const int* in_sizes, int n_in,
                              void* d_out, int out_size) {
    const float* u          = (const float*)d_in[0];
    const float* log_dt     = (const float*)d_in[1];
    const float* C          = (const float*)d_in[2];
    const float* log_A_real = (const float*)d_in[3];
    const float* A_imag     = (const float*)d_in[4];
    const float* D          = (const float*)d_in[5];
    const float* Wm         = (const float*)d_in[6];
    const float* b_conv     = (const float*)d_in[7];
    const float* ln_w       = (const float*)d_in[8];
    const float* ln_b       = (const float*)d_in[9];
    float* out = (float*)d_out;

    cudaFuncSetAttribute(mma_gemm, cudaFuncAttributeMaxDynamicSharedMemorySize, SMEM_BYTES);

    const_kernel<<<64, 256>>>(log_dt, C, log_A_real, A_imag);
    mat_kernel<<<512, 32>>>();
    wcvt_kernel<<<512, 1024>>>(Wm);
    ln_kernel<<<(L_SEQ*B_SZ)/8, 256>>>(u, ln_w, ln_b);
    t1_kernel<<<dim3(64, 16, 16), dim3(32, 8)>>>();
    scan_mega<<<dim3(H_DIM, B_SZ/4), 128>>>(D);
    mma_gemm<<<dim3(L_SEQ/128, H_DIM/64, B_SZ), 256, SMEM_BYTES>>>(b_conv, u, out);
}